// round 12
// baseline (speedup 1.0000x reference)
#include <cuda_runtime.h>
#include <cuda_bf16.h>
#include <cstdint>

// Problem dims (fixed by setup_inputs)
#define BB 2048
#define NN 512
#define DD 256
#define NSTEPS 64
#define BN (BB * NN)

// Persistent scratch (__device__ globals; no runtime alloc)
__device__ float g_ic[BN];
__device__ __nv_bfloat16 g_whi[NN * NN];   // W^T hi split, (n,k) row-major
__device__ __nv_bfloat16 g_wlo[NN * NN];   // W^T lo split
__device__ __nv_bfloat16 g_spk0[BN];       // spike double buffer
__device__ __nv_bfloat16 g_spk1[BN];
__device__ unsigned g_grp[16];             // per-row-group step counters

// ---------------------------------------------------------------- helpers
__device__ __forceinline__ uint32_t smem_u32(const void* p) {
    uint32_t a;
    asm("{ .reg .u64 t; cvta.to.shared.u64 t, %1; cvt.u32.u64 %0, t; }" : "=r"(a) : "l"(p));
    return a;
}
__device__ __forceinline__ void cp16(uint32_t dst, const void* src) {
    asm volatile("cp.async.cg.shared.global [%0], [%1], 16;" :: "r"(dst), "l"(src));
}
#define CP_COMMIT() asm volatile("cp.async.commit_group;")
#define CP_WAIT(n)  asm volatile("cp.async.wait_group %0;" :: "n"(n))

#define LDSM_X4(r0, r1, r2, r3, addr) \
    asm volatile("ldmatrix.sync.aligned.m8n8.x4.shared.b16 {%0,%1,%2,%3}, [%4];" \
                 : "=r"(r0), "=r"(r1), "=r"(r2), "=r"(r3) : "r"(addr))

#define MMA16816(d, a0, a1, a2, a3, b0, b1) \
    asm volatile("mma.sync.aligned.m16n8k16.row.col.f32.bf16.bf16.f32 " \
                 "{%0,%1,%2,%3}, {%4,%5,%6,%7}, {%8,%9}, {%0,%1,%2,%3};" \
                 : "+f"((d)[0]), "+f"((d)[1]), "+f"((d)[2]), "+f"((d)[3]) \
                 : "r"(a0), "r"(a1), "r"(a2), "r"(a3), "r"(b0), "r"(b1))

#define SWZ(o) ((o) ^ (((o) >> 3) & 0x70))

__device__ __forceinline__ unsigned ld_acq(const unsigned* p) {
    unsigned v;
    asm volatile("ld.acquire.gpu.u32 %0, [%1];" : "=r"(v) : "l"(p) : "memory");
    return v;
}

// ---------------------------------------------------------------- init: spikes(step0) + counters
__global__ void init_kernel(const float* __restrict__ c0) {
    int i = (blockIdx.x * blockDim.x + threadIdx.x) * 4;
    float4 c = *(const float4*)&c0[i];
    uint32_t p0 = (c.x > 0.f ? 0x3F80u : 0u) | (c.y > 0.f ? 0x3F800000u : 0u);
    uint32_t p1 = (c.z > 0.f ? 0x3F80u : 0u) | (c.w > 0.f ? 0x3F800000u : 0u);
    *(uint2*)&g_spk0[i] = make_uint2(p0, p1);
    if (blockIdx.x == 0 && threadIdx.x < 16) g_grp[threadIdx.x] = 0;
}

// ---------------- prep: W^T 2-way bf16 split (tiled transpose) ----------------
__global__ __launch_bounds__(256) void prep_kernel(const float* __restrict__ W) {
    __shared__ float t[32][33];
    int n0 = blockIdx.x * 32, k0 = blockIdx.y * 32;
    int tx = threadIdx.x, ty = threadIdx.y;
#pragma unroll
    for (int i = 0; i < 4; i++)
        t[ty + i * 8][tx] = W[(k0 + ty + i * 8) * NN + n0 + tx];
    __syncthreads();
#pragma unroll
    for (int i = 0; i < 4; i++) {
        float w = t[tx][ty + i * 8];
        __nv_bfloat16 hi = __float2bfloat16(w);
        __nv_bfloat16 lo = __float2bfloat16(w - __bfloat162float(hi));
        int n = n0 + ty + i * 8, k = k0 + tx;
        g_whi[n * NN + k] = hi;
        g_wlo[n * NN + k] = lo;
    }
}

// ---------------- input current: IC = rates @ iw^T (one-time) ----------------
__global__ __launch_bounds__(256) void ic_kernel(const float* __restrict__ rates,
                                                 const float* __restrict__ iw) {
    __shared__ float As[64][33];
    __shared__ float Bs[64][33];
    int bm = blockIdx.x * 64, bn = blockIdx.y * 64;
    int tid = threadIdx.x;
    int tx = tid & 15, ty = tid >> 4;
    float acc[4][4] = {};
    for (int k0 = 0; k0 < DD; k0 += 32) {
#pragma unroll
        for (int t = 0; t < 2; t++) {
            int idx = tid + t * 256;
            int r = idx >> 3, q = idx & 7;
            float4 a = *(const float4*)&rates[(bm + r) * DD + k0 + q * 4];
            As[r][q * 4 + 0] = a.x; As[r][q * 4 + 1] = a.y;
            As[r][q * 4 + 2] = a.z; As[r][q * 4 + 3] = a.w;
            float4 b = *(const float4*)&iw[(bn + r) * DD + k0 + q * 4];
            Bs[r][q * 4 + 0] = b.x; Bs[r][q * 4 + 1] = b.y;
            Bs[r][q * 4 + 2] = b.z; Bs[r][q * 4 + 3] = b.w;
        }
        __syncthreads();
#pragma unroll
        for (int k = 0; k < 32; k++) {
            float a[4], b[4];
#pragma unroll
            for (int i = 0; i < 4; i++) a[i] = As[ty * 4 + i][k];
#pragma unroll
            for (int j = 0; j < 4; j++) b[j] = Bs[tx * 4 + j][k];
#pragma unroll
            for (int i = 0; i < 4; i++)
#pragma unroll
                for (int j = 0; j < 4; j++)
                    acc[i][j] = fmaf(a[i], b[j], acc[i][j]);
        }
        __syncthreads();
    }
#pragma unroll
    for (int i = 0; i < 4; i++)
#pragma unroll
        for (int j = 0; j < 4; j++)
            g_ic[(bm + ty * 4 + i) * NN + bn + tx * 4 + j] = acc[i][j];
}

// ---------------- persistent fused LSM kernel ----------------
// grid (16,8) = 128 CTAs (one per SM, 160KB smem), 512 threads = 16 warps (8m x 2n),
// warp tile 16x32. Per-row-group (8 CTA) sync instead of grid barrier.
// Smem: A stage0 16KB @0, A stage1 16KB @16384, Bhi 64KB @32768, Blo 64KB @98304.
#define A_ST0 0
#define A_ST1 16384
#define B_HI 32768
#define B_LO 98304
#define LSM_SMEM 163840

__global__ __launch_bounds__(512, 1) void lsm_kernel(const float* __restrict__ v0,
                                                     const float* __restrict__ c0,
                                                     float* __restrict__ out) {
    extern __shared__ __align__(1024) char smem[];
    uint32_t sb = smem_u32(smem);
    int tid = threadIdx.x;
    int wid = tid >> 5, lane = tid & 31;
    int bm = blockIdx.x * 128;
    int bn = blockIdx.y * 64;
    int warp_m = wid & 7, warp_n = wid >> 3;
    int tq = lane >> 2, tr = lane & 3;

    // ---- one-time: load resident B strips (both splits, all 8 k-chunks) ----
    for (int chunk = 0; chunk < 8; chunk++) {
        int k0 = chunk * 64;
        int r = tid >> 3, q = tid & 7;              // 512 threads = 64 rows x 8 quads
        uint32_t d = (uint32_t)(chunk * 8192) + SWZ((uint32_t)(r * 128 + q * 16));
        cp16(sb + B_HI + d, &g_whi[(bn + r) * NN + k0 + q * 8]);
        cp16(sb + B_LO + d, &g_wlo[(bn + r) * NN + k0 + q * 8]);
    }

    // ---- one-time: register state, 16 elems/thread ----
    float c_r[16], v_r[16], ic_r[16], ss_r[16];
#pragma unroll
    for (int j = 0; j < 4; j++)
#pragma unroll
        for (int h = 0; h < 2; h++) {
            int st = (j * 2 + h) * 2;
            int row = bm + warp_m * 16 + h * 8 + tq;
            int col = bn + warp_n * 32 + j * 8 + tr * 2;
            int idx = row * NN + col;
            float2 cc = *(const float2*)&c0[idx];
            float2 vv = *(const float2*)&v0[idx];
            float2 ii = *(const float2*)&g_ic[idx];
            c_r[st] = cc.x;  c_r[st + 1] = cc.y;
            v_r[st] = vv.x;  v_r[st + 1] = vv.y;
            ic_r[st] = ii.x; ic_r[st + 1] = ii.y;
            ss_r[st] = 0.f;  ss_r[st + 1] = 0.f;
        }

    const float AS = 0.81873075307798182f;
    const float OS = 0.18126924692201818f;
    const float AM = 0.95122942450071403f;
    const float OM = 0.04877057549928599f;

    for (int s = 0; s < NSTEPS; s++) {
        const __nv_bfloat16* __restrict__ spk_in  = (s & 1) ? g_spk1 : g_spk0;
        __nv_bfloat16* __restrict__       spk_out = (s & 1) ? g_spk0 : g_spk1;

        float acc[4][4];
#pragma unroll
        for (int j = 0; j < 4; j++)
#pragma unroll
            for (int e = 0; e < 4; e++) acc[j][e] = 0.f;

        auto issueA = [&](int chunk) {
            uint32_t so = sb + ((chunk & 1) ? A_ST1 : A_ST0);
            int k0 = chunk * 64;
#pragma unroll
            for (int t = 0; t < 2; t++) {           // 1024 16B elems / 512 threads
                int idx = tid + t * 512;
                int r = idx >> 3, q = idx & 7;
                cp16(so + SWZ((uint32_t)(r * 128 + q * 16)),
                     &spk_in[(bm + r) * NN + k0 + q * 8]);
            }
            CP_COMMIT();
        };

        issueA(0);
        for (int chunk = 0; chunk < 8; chunk++) {
            if (chunk + 1 < 8) { issueA(chunk + 1); CP_WAIT(1); }
            else               { CP_WAIT(0); }
            __syncthreads();

            uint32_t Ab = sb + ((chunk & 1) ? A_ST1 : A_ST0);
            uint32_t Bh = sb + B_HI + chunk * 8192;
            uint32_t Bl = sb + B_LO + chunk * 8192;
#pragma unroll
            for (int kk = 0; kk < 64; kk += 16) {
                uint32_t a0, a1, a2, a3;
                {
                    uint32_t off = (uint32_t)((warp_m * 16 + (lane & 15)) * 128 +
                                              (kk + (lane >> 4) * 8) * 2);
                    LDSM_X4(a0, a1, a2, a3, Ab + SWZ(off));
                }
                int mtx = lane >> 3;
                uint32_t boff[2];
#pragma unroll
                for (int pair = 0; pair < 2; pair++) {
                    int j = pair * 2 + (mtx >> 1);
                    int khalf = mtx & 1;
                    boff[pair] = SWZ((uint32_t)((warp_n * 32 + j * 8 + (lane & 7)) * 128 +
                                                (kk + khalf * 8) * 2));
                }
                uint32_t b[4][2];
#pragma unroll
                for (int pair = 0; pair < 2; pair++) {
                    uint32_t r0, r1, r2, r3;
                    LDSM_X4(r0, r1, r2, r3, Bh + boff[pair]);
                    b[pair * 2 + 0][0] = r0; b[pair * 2 + 0][1] = r1;
                    b[pair * 2 + 1][0] = r2; b[pair * 2 + 1][1] = r3;
                }
#pragma unroll
                for (int j = 0; j < 4; j++)
                    MMA16816(acc[j], a0, a1, a2, a3, b[j][0], b[j][1]);
#pragma unroll
                for (int pair = 0; pair < 2; pair++) {
                    uint32_t r0, r1, r2, r3;
                    LDSM_X4(r0, r1, r2, r3, Bl + boff[pair]);
                    b[pair * 2 + 0][0] = r0; b[pair * 2 + 0][1] = r1;
                    b[pair * 2 + 1][0] = r2; b[pair * 2 + 1][1] = r3;
                }
#pragma unroll
                for (int j = 0; j < 4; j++)
                    MMA16816(acc[j], a0, a1, a2, a3, b[j][0], b[j][1]);
            }
            __syncthreads();
        }

        // ---- epilogue: register-state update + spike write ----
#pragma unroll
        for (int j = 0; j < 4; j++)
#pragma unroll
            for (int h = 0; h < 2; h++) {
                int st = (j * 2 + h) * 2;
                float r0 = acc[j][h * 2 + 0];
                float r1 = acc[j][h * 2 + 1];
                c_r[st]     = AS * c_r[st]     + OS * (ic_r[st]     + r0);
                c_r[st + 1] = AS * c_r[st + 1] + OS * (ic_r[st + 1] + r1);
                v_r[st]     = AM * v_r[st]     + OM * c_r[st];
                v_r[st + 1] = AM * v_r[st + 1] + OM * c_r[st + 1];
                ss_r[st]     += (v_r[st]     > 0.f) ? 1.f : 0.f;
                ss_r[st + 1] += (v_r[st + 1] > 0.f) ? 1.f : 0.f;
                int row = bm + warp_m * 16 + h * 8 + tq;
                int col = bn + warp_n * 32 + j * 8 + tr * 2;
                uint32_t sp = (c_r[st] > 0.f ? 0x3F80u : 0u) |
                              (c_r[st + 1] > 0.f ? 0x3F800000u : 0u);
                *(uint32_t*)&spk_out[row * NN + col] = sp;
            }

        // ---- per-row-group sync (8 CTAs sharing blockIdx.x) ----
        if (s + 1 < NSTEPS) {
            __syncthreads();
            if (tid == 0) {
                asm volatile("red.release.gpu.add.u32 [%0], 1;"
                             :: "l"(&g_grp[blockIdx.x]) : "memory");
                unsigned target = 8u * (unsigned)(s + 1);
                while (ld_acq(&g_grp[blockIdx.x]) < target) __nanosleep(20);
            }
            __syncthreads();
        }
    }

    // ---- final output: [readout | v | c] ----
    const float inv = 1.0f / (float)NSTEPS;
#pragma unroll
    for (int j = 0; j < 4; j++)
#pragma unroll
        for (int h = 0; h < 2; h++) {
            int st = (j * 2 + h) * 2;
            int row = bm + warp_m * 16 + h * 8 + tq;
            int col = bn + warp_n * 32 + j * 8 + tr * 2;
            int idx = row * NN + col;
            *(float2*)&out[idx]          = make_float2(ss_r[st] * inv, ss_r[st + 1] * inv);
            *(float2*)&out[BN + idx]     = make_float2(v_r[st], v_r[st + 1]);
            *(float2*)&out[2 * BN + idx] = make_float2(c_r[st], c_r[st + 1]);
        }
}

extern "C" void kernel_launch(void* const* d_in, const int* in_sizes, int n_in,
                              void* d_out, int out_size) {
    const float* rates = (const float*)d_in[0];
    const float* iw    = (const float*)d_in[1];
    const float* W     = (const float*)d_in[2];
    const float* v0    = (const float*)d_in[3];
    const float* c0    = (const float*)d_in[4];
    float* out = (float*)d_out;

    cudaFuncSetAttribute(lsm_kernel, cudaFuncAttributeMaxDynamicSharedMemorySize, LSM_SMEM);

    init_kernel<<<BN / 1024, 256>>>(c0);
    prep_kernel<<<dim3(NN / 32, NN / 32), dim3(32, 8)>>>(W);
    ic_kernel<<<dim3(BB / 64, NN / 64), 256>>>(rates, iw);
    lsm_kernel<<<dim3(BB / 128, NN / 64), 512, LSM_SMEM>>>(v0, c0, out);
}

// round 13
// speedup vs baseline: 1.2656x; 1.2656x over previous
#include <cuda_runtime.h>
#include <cuda_bf16.h>
#include <cstdint>

// Problem dims (fixed by setup_inputs)
#define BB 2048
#define NN 512
#define DD 256
#define NSTEPS 64
#define BN (BB * NN)

// Persistent scratch (__device__ globals; no runtime alloc)
__device__ float g_ic[BN];
__device__ __nv_bfloat16 g_whi[NN * NN];   // W^T hi split, (n,k) row-major
__device__ __nv_bfloat16 g_wlo[NN * NN];   // W^T lo split
__device__ __nv_bfloat16 g_spk0[BN];       // spike double buffer
__device__ __nv_bfloat16 g_spk1[BN];
__device__ unsigned g_grp[16];             // per-row-group step counters

// ---------------------------------------------------------------- helpers
__device__ __forceinline__ uint32_t smem_u32(const void* p) {
    uint32_t a;
    asm("{ .reg .u64 t; cvta.to.shared.u64 t, %1; cvt.u32.u64 %0, t; }" : "=r"(a) : "l"(p));
    return a;
}
__device__ __forceinline__ void cp16(uint32_t dst, const void* src) {
    asm volatile("cp.async.cg.shared.global [%0], [%1], 16;" :: "r"(dst), "l"(src));
}
#define CP_COMMIT() asm volatile("cp.async.commit_group;")
#define CP_WAIT(n)  asm volatile("cp.async.wait_group %0;" :: "n"(n))

#define LDSM_X4(r0, r1, r2, r3, addr) \
    asm volatile("ldmatrix.sync.aligned.m8n8.x4.shared.b16 {%0,%1,%2,%3}, [%4];" \
                 : "=r"(r0), "=r"(r1), "=r"(r2), "=r"(r3) : "r"(addr))

#define MMA16816(d, a0, a1, a2, a3, b0, b1) \
    asm volatile("mma.sync.aligned.m16n8k16.row.col.f32.bf16.bf16.f32 " \
                 "{%0,%1,%2,%3}, {%4,%5,%6,%7}, {%8,%9}, {%0,%1,%2,%3};" \
                 : "+f"((d)[0]), "+f"((d)[1]), "+f"((d)[2]), "+f"((d)[3]) \
                 : "r"(a0), "r"(a1), "r"(a2), "r"(a3), "r"(b0), "r"(b1))

#define SWZ(o) ((o) ^ (((o) >> 3) & 0x70))

__device__ __forceinline__ unsigned ld_acq(const unsigned* p) {
    unsigned v;
    asm volatile("ld.acquire.gpu.u32 %0, [%1];" : "=r"(v) : "l"(p) : "memory");
    return v;
}

// ---------------------------------------------------------------- init: spikes(step0) + counters
__global__ void init_kernel(const float* __restrict__ c0) {
    int i = (blockIdx.x * blockDim.x + threadIdx.x) * 4;
    float4 c = *(const float4*)&c0[i];
    uint32_t p0 = (c.x > 0.f ? 0x3F80u : 0u) | (c.y > 0.f ? 0x3F800000u : 0u);
    uint32_t p1 = (c.z > 0.f ? 0x3F80u : 0u) | (c.w > 0.f ? 0x3F800000u : 0u);
    *(uint2*)&g_spk0[i] = make_uint2(p0, p1);
    if (blockIdx.x == 0 && threadIdx.x < 16) g_grp[threadIdx.x] = 0;
}

// ---------------- prep: W^T 2-way bf16 split (tiled transpose) ----------------
__global__ __launch_bounds__(256) void prep_kernel(const float* __restrict__ W) {
    __shared__ float t[32][33];
    int n0 = blockIdx.x * 32, k0 = blockIdx.y * 32;
    int tx = threadIdx.x, ty = threadIdx.y;
#pragma unroll
    for (int i = 0; i < 4; i++)
        t[ty + i * 8][tx] = W[(k0 + ty + i * 8) * NN + n0 + tx];
    __syncthreads();
#pragma unroll
    for (int i = 0; i < 4; i++) {
        float w = t[tx][ty + i * 8];
        __nv_bfloat16 hi = __float2bfloat16(w);
        __nv_bfloat16 lo = __float2bfloat16(w - __bfloat162float(hi));
        int n = n0 + ty + i * 8, k = k0 + tx;
        g_whi[n * NN + k] = hi;
        g_wlo[n * NN + k] = lo;
    }
}

// ---------------- input current: IC = rates @ iw^T (one-time) ----------------
__global__ __launch_bounds__(256) void ic_kernel(const float* __restrict__ rates,
                                                 const float* __restrict__ iw) {
    __shared__ float As[64][33];
    __shared__ float Bs[64][33];
    int bm = blockIdx.x * 64, bn = blockIdx.y * 64;
    int tid = threadIdx.x;
    int tx = tid & 15, ty = tid >> 4;
    float acc[4][4] = {};
    for (int k0 = 0; k0 < DD; k0 += 32) {
#pragma unroll
        for (int t = 0; t < 2; t++) {
            int idx = tid + t * 256;
            int r = idx >> 3, q = idx & 7;
            float4 a = *(const float4*)&rates[(bm + r) * DD + k0 + q * 4];
            As[r][q * 4 + 0] = a.x; As[r][q * 4 + 1] = a.y;
            As[r][q * 4 + 2] = a.z; As[r][q * 4 + 3] = a.w;
            float4 b = *(const float4*)&iw[(bn + r) * DD + k0 + q * 4];
            Bs[r][q * 4 + 0] = b.x; Bs[r][q * 4 + 1] = b.y;
            Bs[r][q * 4 + 2] = b.z; Bs[r][q * 4 + 3] = b.w;
        }
        __syncthreads();
#pragma unroll
        for (int k = 0; k < 32; k++) {
            float a[4], b[4];
#pragma unroll
            for (int i = 0; i < 4; i++) a[i] = As[ty * 4 + i][k];
#pragma unroll
            for (int j = 0; j < 4; j++) b[j] = Bs[tx * 4 + j][k];
#pragma unroll
            for (int i = 0; i < 4; i++)
#pragma unroll
                for (int j = 0; j < 4; j++)
                    acc[i][j] = fmaf(a[i], b[j], acc[i][j]);
        }
        __syncthreads();
    }
#pragma unroll
    for (int i = 0; i < 4; i++)
#pragma unroll
        for (int j = 0; j < 4; j++)
            g_ic[(bm + ty * 4 + i) * NN + bn + tx * 4 + j] = acc[i][j];
}

// ---------------- persistent fused LSM kernel ----------------
// grid (16,8) = 128 CTAs, 256 threads = 8 warps (4m x 2n), warp tile 32x32.
// k chunks of 128 (4/step), 3 A stages of 32KB. Smem: A @0 (3x32KB), Bhi @98304, Blo @163840.
// Per-row-group (8 CTA) sync; 5 syncthreads/step.
#define A_STG(i) ((i) * 32768)
#define B_HI 98304
#define B_LO 163840
#define LSM_SMEM 229376

__global__ __launch_bounds__(256, 1) void lsm_kernel(const float* __restrict__ v0,
                                                     const float* __restrict__ c0,
                                                     float* __restrict__ out) {
    extern __shared__ __align__(1024) char smem[];
    uint32_t sb = smem_u32(smem);
    int tid = threadIdx.x;
    int wid = tid >> 5, lane = tid & 31;
    int bm = blockIdx.x * 128;
    int bn = blockIdx.y * 64;
    int warp_m = wid & 3, warp_n = wid >> 2;
    int tq = lane >> 2, tr = lane & 3;

    // ---- one-time: resident B strips (both splits, 8 k-blocks of 64) ----
    for (int kb = 0; kb < 8; kb++) {
        int k0 = kb * 64;
#pragma unroll
        for (int t = 0; t < 2; t++) {
            int idx = tid + t * 256;
            int r = idx >> 3, q = idx & 7;
            uint32_t d = (uint32_t)(kb * 8192) + SWZ((uint32_t)(r * 128 + q * 16));
            cp16(sb + B_HI + d, &g_whi[(bn + r) * NN + k0 + q * 8]);
            cp16(sb + B_LO + d, &g_wlo[(bn + r) * NN + k0 + q * 8]);
        }
    }
    // (B copies join the first commit group below)

    // ---- one-time: register state, 32 elems/thread ----
    float c_r[32], v_r[32], ic_r[32], ss_r[32];
#pragma unroll
    for (int i = 0; i < 2; i++)
#pragma unroll
        for (int j = 0; j < 4; j++)
#pragma unroll
            for (int h = 0; h < 2; h++) {
                int st = ((i * 4 + j) * 2 + h) * 2;
                int row = bm + warp_m * 32 + i * 16 + h * 8 + tq;
                int col = bn + warp_n * 32 + j * 8 + tr * 2;
                int idx = row * NN + col;
                float2 cc = *(const float2*)&c0[idx];
                float2 vv = *(const float2*)&v0[idx];
                float2 ii = *(const float2*)&g_ic[idx];
                c_r[st] = cc.x;  c_r[st + 1] = cc.y;
                v_r[st] = vv.x;  v_r[st + 1] = vv.y;
                ic_r[st] = ii.x; ic_r[st + 1] = ii.y;
                ss_r[st] = 0.f;  ss_r[st + 1] = 0.f;
            }

    const float AS = 0.81873075307798182f;
    const float OS = 0.18126924692201818f;
    const float AM = 0.95122942450071403f;
    const float OM = 0.04877057549928599f;

    for (int s = 0; s < NSTEPS; s++) {
        const __nv_bfloat16* __restrict__ spk_in  = (s & 1) ? g_spk1 : g_spk0;
        __nv_bfloat16* __restrict__       spk_out = (s & 1) ? g_spk0 : g_spk1;

        float acc[2][4][4];
#pragma unroll
        for (int i = 0; i < 2; i++)
#pragma unroll
            for (int j = 0; j < 4; j++)
#pragma unroll
                for (int e = 0; e < 4; e++) acc[i][j][e] = 0.f;

        // A chunk issue: 128 rows x 128 k bf16 = 32KB into stage (c<3 ? c : 0)
        auto issueA = [&](int c) {
            uint32_t so = sb + A_STG(c < 3 ? c : 0);
            int k0 = c * 128;
#pragma unroll
            for (int t = 0; t < 8; t++) {
                int idx = tid + t * 256;            // 0..2047
                int r = idx >> 4, q = idx & 15;     // 128 rows x 16 k-quads(8 elems)
                uint32_t d = (uint32_t)((q >> 3) * 16384) +
                             SWZ((uint32_t)(r * 128 + (q & 7) * 16));
                cp16(so + d, &spk_in[(bm + r) * NN + k0 + q * 8]);
            }
            CP_COMMIT();
        };

        issueA(0);   // + resident-B copies on s==0 ride in this group
        issueA(1);
        issueA(2);

        // compute one 128-k chunk from stage
        auto compute = [&](int c) {
            uint32_t Ab = sb + A_STG(c < 3 ? c : 0);
#pragma unroll
            for (int kk = 0; kk < 128; kk += 16) {
                int half = kk >> 6, kkl = kk & 63;
                int kblk = c * 2 + half;
                uint32_t Ah = Ab + half * 16384;
                uint32_t Bh = sb + B_HI + kblk * 8192;
                uint32_t Bl = sb + B_LO + kblk * 8192;
                uint32_t a[2][4];
#pragma unroll
                for (int i = 0; i < 2; i++) {
                    uint32_t off = (uint32_t)((warp_m * 32 + i * 16 + (lane & 15)) * 128 +
                                              (kkl + (lane >> 4) * 8) * 2);
                    LDSM_X4(a[i][0], a[i][1], a[i][2], a[i][3], Ah + SWZ(off));
                }
                int mtx = lane >> 3;
                uint32_t boff[2];
#pragma unroll
                for (int pair = 0; pair < 2; pair++) {
                    int j = pair * 2 + (mtx >> 1);
                    int khalf = mtx & 1;
                    boff[pair] = SWZ((uint32_t)((warp_n * 32 + j * 8 + (lane & 7)) * 128 +
                                                (kkl + khalf * 8) * 2));
                }
                uint32_t b[4][2];
#pragma unroll
                for (int pair = 0; pair < 2; pair++) {
                    uint32_t r0, r1, r2, r3;
                    LDSM_X4(r0, r1, r2, r3, Bh + boff[pair]);
                    b[pair * 2 + 0][0] = r0; b[pair * 2 + 0][1] = r1;
                    b[pair * 2 + 1][0] = r2; b[pair * 2 + 1][1] = r3;
                }
#pragma unroll
                for (int i = 0; i < 2; i++)
#pragma unroll
                    for (int j = 0; j < 4; j++)
                        MMA16816(acc[i][j], a[i][0], a[i][1], a[i][2], a[i][3], b[j][0], b[j][1]);
#pragma unroll
                for (int pair = 0; pair < 2; pair++) {
                    uint32_t r0, r1, r2, r3;
                    LDSM_X4(r0, r1, r2, r3, Bl + boff[pair]);
                    b[pair * 2 + 0][0] = r0; b[pair * 2 + 0][1] = r1;
                    b[pair * 2 + 1][0] = r2; b[pair * 2 + 1][1] = r3;
                }
#pragma unroll
                for (int i = 0; i < 2; i++)
#pragma unroll
                    for (int j = 0; j < 4; j++)
                        MMA16816(acc[i][j], a[i][0], a[i][1], a[i][2], a[i][3], b[j][0], b[j][1]);
            }
        };

        CP_WAIT(2); __syncthreads();
        compute(0);
        __syncthreads();            // stage0 consumed
        issueA(3);                  // refill stage0 with chunk3
        CP_WAIT(2); __syncthreads();
        compute(1);
        CP_WAIT(1); __syncthreads();
        compute(2);
        CP_WAIT(0); __syncthreads();
        compute(3);

        // ---- epilogue part 1: c update + spike store ----
#pragma unroll
        for (int i = 0; i < 2; i++)
#pragma unroll
            for (int j = 0; j < 4; j++)
#pragma unroll
                for (int h = 0; h < 2; h++) {
                    int st = ((i * 4 + j) * 2 + h) * 2;
                    float r0 = acc[i][j][h * 2 + 0];
                    float r1 = acc[i][j][h * 2 + 1];
                    c_r[st]     = AS * c_r[st]     + OS * (ic_r[st]     + r0);
                    c_r[st + 1] = AS * c_r[st + 1] + OS * (ic_r[st + 1] + r1);
                    int row = bm + warp_m * 32 + i * 16 + h * 8 + tq;
                    int col = bn + warp_n * 32 + j * 8 + tr * 2;
                    uint32_t sp = (c_r[st] > 0.f ? 0x3F80u : 0u) |
                                  (c_r[st + 1] > 0.f ? 0x3F800000u : 0u);
                    *(uint32_t*)&spk_out[row * NN + col] = sp;
                }

        // ---- arrive early, overlap v/ss math with peer arrivals ----
        bool more = (s + 1 < NSTEPS);
        if (more) {
            __syncthreads();
            if (tid == 0)
                asm volatile("red.release.gpu.add.u32 [%0], 1;"
                             :: "l"(&g_grp[blockIdx.x]) : "memory");
        }

        // ---- epilogue part 2: v / spike-count (independent of peers) ----
#pragma unroll
        for (int e = 0; e < 32; e++) {
            v_r[e] = AM * v_r[e] + OM * c_r[e];
            ss_r[e] += (v_r[e] > 0.f) ? 1.f : 0.f;
        }

        if (more) {
            if (tid == 0) {
                unsigned target = 8u * (unsigned)(s + 1);
                while (ld_acq(&g_grp[blockIdx.x]) < target) __nanosleep(20);
            }
            __syncthreads();
        }
    }

    // ---- final output: [readout | v | c] ----
    const float inv = 1.0f / (float)NSTEPS;
#pragma unroll
    for (int i = 0; i < 2; i++)
#pragma unroll
        for (int j = 0; j < 4; j++)
#pragma unroll
            for (int h = 0; h < 2; h++) {
                int st = ((i * 4 + j) * 2 + h) * 2;
                int row = bm + warp_m * 32 + i * 16 + h * 8 + tq;
                int col = bn + warp_n * 32 + j * 8 + tr * 2;
                int idx = row * NN + col;
                *(float2*)&out[idx]          = make_float2(ss_r[st] * inv, ss_r[st + 1] * inv);
                *(float2*)&out[BN + idx]     = make_float2(v_r[st], v_r[st + 1]);
                *(float2*)&out[2 * BN + idx] = make_float2(c_r[st], c_r[st + 1]);
            }
}

extern "C" void kernel_launch(void* const* d_in, const int* in_sizes, int n_in,
                              void* d_out, int out_size) {
    const float* rates = (const float*)d_in[0];
    const float* iw    = (const float*)d_in[1];
    const float* W     = (const float*)d_in[2];
    const float* v0    = (const float*)d_in[3];
    const float* c0    = (const float*)d_in[4];
    float* out = (float*)d_out;

    cudaFuncSetAttribute(lsm_kernel, cudaFuncAttributeMaxDynamicSharedMemorySize, LSM_SMEM);

    init_kernel<<<BN / 1024, 256>>>(c0);
    prep_kernel<<<dim3(NN / 32, NN / 32), dim3(32, 8)>>>(W);
    ic_kernel<<<dim3(BB / 64, NN / 64), 256>>>(rates, iw);
    lsm_kernel<<<dim3(BB / 128, NN / 64), 256, LSM_SMEM>>>(v0, c0, out);
}